// round 1
// baseline (speedup 1.0000x reference)
#include <cuda_runtime.h>
#include <cuda_bf16.h>
#include <cstdint>

#define N_USERS 100000
#define N_ITEMS 200000
#define N_NODES 300000
#define EMB     64
#define NNZ     9600000
#define SCAN_B  1024
#define NB      ((N_NODES + SCAN_B - 1) / SCAN_B)   // 293

// -------- static device scratch (allocation-free) --------
__device__ float g_ego[2][(size_t)N_NODES * EMB];  // ping-pong layer embeddings
__device__ int   g_col[NNZ];
__device__ float g_val[NNZ];
__device__ int   g_rowptr[N_NODES + 1];
__device__ int   g_cursor[N_NODES];
__device__ int   g_counts[N_NODES];
__device__ int   g_bsums[NB];

// -------- 1) zero counts --------
__global__ void k_zero_counts() {
    int i = blockIdx.x * blockDim.x + threadIdx.x;
    if (i < N_NODES) g_counts[i] = 0;
}

// -------- 2) init ego0 and acc(=d_out) from user/item embeddings --------
__global__ void k_init(const float4* __restrict__ user4,
                       const float4* __restrict__ item4,
                       float4* __restrict__ out4) {
    const int n4 = N_NODES * EMB / 4;          // 4.8M float4
    const int nu4 = N_USERS * EMB / 4;         // 1.6M
    int i = blockIdx.x * blockDim.x + threadIdx.x;
    if (i >= n4) return;
    float4 v = (i < nu4) ? user4[i] : item4[i - nu4];
    reinterpret_cast<float4*>(g_ego[0])[i] = v;
    out4[i] = v;                               // acc starts at layer-0 embedding
}

// -------- 3) histogram of rows --------
__global__ void k_hist(const int* __restrict__ rows) {
    int e = blockIdx.x * blockDim.x + threadIdx.x;
    if (e < NNZ) atomicAdd(&g_counts[rows[e]], 1);
}

// -------- 4) exclusive scan (3 kernels) --------
__global__ void k_scan1() {
    __shared__ int sh[SCAN_B];
    int tid = threadIdx.x;
    int gid = blockIdx.x * SCAN_B + tid;
    int v = (gid < N_NODES) ? g_counts[gid] : 0;
    sh[tid] = v;
    __syncthreads();
    for (int off = 1; off < SCAN_B; off <<= 1) {
        int t = (tid >= off) ? sh[tid - off] : 0;
        __syncthreads();
        sh[tid] += t;
        __syncthreads();
    }
    int incl = sh[tid];
    if (gid < N_NODES) g_rowptr[gid] = incl - v;     // block-local exclusive
    if (tid == SCAN_B - 1) g_bsums[blockIdx.x] = incl;
}

__global__ void k_scan2() {
    __shared__ int sh[512];
    int tid = threadIdx.x;   // blockDim = 512, NB = 293 <= 512
    int v = (tid < NB) ? g_bsums[tid] : 0;
    sh[tid] = v;
    __syncthreads();
    for (int off = 1; off < 512; off <<= 1) {
        int t = (tid >= off) ? sh[tid - off] : 0;
        __syncthreads();
        sh[tid] += t;
        __syncthreads();
    }
    if (tid < NB) g_bsums[tid] = sh[tid] - v;        // exclusive
}

__global__ void k_scan3() {
    int gid = blockIdx.x * SCAN_B + threadIdx.x;
    if (gid < N_NODES) {
        int p = g_rowptr[gid] + g_bsums[blockIdx.x];
        g_rowptr[gid] = p;
        g_cursor[gid] = p;                            // scatter cursors start at row base
    }
    if (gid == 0) g_rowptr[N_NODES] = NNZ;
}

// -------- 5) scatter COO -> CSR --------
__global__ void k_scatter(const int* __restrict__ rows,
                          const int* __restrict__ cols,
                          const float* __restrict__ vals) {
    int e = blockIdx.x * blockDim.x + threadIdx.x;
    if (e >= NNZ) return;
    int r = rows[e];
    int idx = atomicAdd(&g_cursor[r], 1);
    g_col[idx] = cols[e];
    g_val[idx] = vals[e];
}

// -------- 6) warp-per-row SpMM: eout[r] = sum val*ein[col]; acc += eout --------
__global__ __launch_bounds__(256) void k_spmm(int pin, float2* __restrict__ acc) {
    const float2* __restrict__ ein = reinterpret_cast<const float2*>(g_ego[pin]);
    float2* __restrict__ eout      = reinterpret_cast<float2*>(g_ego[1 - pin]);

    int warp = (blockIdx.x * blockDim.x + threadIdx.x) >> 5;
    int lane = threadIdx.x & 31;
    if (warp >= N_NODES) return;

    int start = g_rowptr[warp];
    int end   = g_rowptr[warp + 1];

    float2 a = make_float2(0.f, 0.f);

    for (int base = start; base < end; base += 32) {
        int rem = end - base;
        int c = 0; float v = 0.f;
        if (lane < rem) {                 // coalesced meta load for up to 32 edges
            c = g_col[base + lane];
            v = g_val[base + lane];
        }
        if (rem >= 32) {
            #pragma unroll
            for (int j = 0; j < 32; j++) {
                int   cj = __shfl_sync(0xffffffffu, c, j);
                float vj = __shfl_sync(0xffffffffu, v, j);
                float2 x = __ldg(ein + (size_t)cj * 32 + lane);  // coalesced 256B gather
                a.x = fmaf(vj, x.x, a.x);
                a.y = fmaf(vj, x.y, a.y);
            }
        } else {
            for (int j = 0; j < rem; j++) {
                int   cj = __shfl_sync(0xffffffffu, c, j);
                float vj = __shfl_sync(0xffffffffu, v, j);
                float2 x = __ldg(ein + (size_t)cj * 32 + lane);
                a.x = fmaf(vj, x.x, a.x);
                a.y = fmaf(vj, x.y, a.y);
            }
        }
    }

    size_t o = (size_t)warp * 32 + lane;
    eout[o] = a;
    float2 t = acc[o];
    t.x += a.x; t.y += a.y;
    acc[o] = t;
}

// -------- 7) final scale by 1/(L+1) = 0.25 --------
__global__ void k_scale(float4* __restrict__ out4) {
    const int n4 = N_NODES * EMB / 4;
    int i = blockIdx.x * blockDim.x + threadIdx.x;
    if (i >= n4) return;
    float4 v = out4[i];
    v.x *= 0.25f; v.y *= 0.25f; v.z *= 0.25f; v.w *= 0.25f;
    out4[i] = v;
}

extern "C" void kernel_launch(void* const* d_in, const int* in_sizes, int n_in,
                              void* d_out, int out_size) {
    const float* user = (const float*)d_in[0];
    const float* item = (const float*)d_in[1];
    const int*   rows = (const int*)d_in[2];
    const int*   cols = (const int*)d_in[3];
    const float* vals = (const float*)d_in[4];
    float* out = (float*)d_out;

    const int T = 256;
    const int n4      = N_NODES * EMB / 4;
    const int gInit   = (n4 + T - 1) / T;
    const int gNodes  = (N_NODES + T - 1) / T;
    const int gEdges  = (NNZ + T - 1) / T;
    const int gSpmm   = ((N_NODES * 32) + T - 1) / T;

    k_zero_counts<<<gNodes, T>>>();
    k_init<<<gInit, T>>>((const float4*)user, (const float4*)item, (float4*)out);
    k_hist<<<gEdges, T>>>(rows);
    k_scan1<<<NB, SCAN_B>>>();
    k_scan2<<<1, 512>>>();
    k_scan3<<<NB, SCAN_B>>>();
    k_scatter<<<gEdges, T>>>(rows, cols, vals);

    int pin = 0;
    for (int layer = 0; layer < 3; layer++) {
        k_spmm<<<gSpmm, T>>>(pin, (float2*)out);
        pin = 1 - pin;
    }
    k_scale<<<gInit, T>>>((float4*)out);
}

// round 2
// speedup vs baseline: 1.2768x; 1.2768x over previous
#include <cuda_runtime.h>
#include <cuda_fp16.h>
#include <cstdint>

#define N_USERS 100000
#define N_ITEMS 200000
#define N_NODES 300000
#define EMB     64
#define NNZ     9600000
#define SCAN_B  1024
#define NB      ((N_NODES + SCAN_B - 1) / SCAN_B)   // 293

// -------- static device scratch (allocation-free) --------
__device__ __half g_ego[2][(size_t)N_NODES * EMB];   // ping-pong fp16 layer embeddings
__device__ int2   g_edge[NNZ];                       // packed (col, val-bits)
__device__ int    g_rowptr[N_NODES + 1];
__device__ int    g_cursor[N_NODES];
__device__ int    g_counts[N_NODES];
__device__ int    g_bsums[NB];

// -------- 1) zero counts --------
__global__ void k_zero_counts() {
    int i = blockIdx.x * blockDim.x + threadIdx.x;
    if (i < N_NODES) g_counts[i] = 0;
}

// -------- 2) init: acc(=d_out) = ego0 (fp32), g_ego[0] = fp16(ego0) --------
__global__ void k_init(const float4* __restrict__ user4,
                       const float4* __restrict__ item4,
                       float4* __restrict__ out4) {
    const int n4  = N_NODES * EMB / 4;         // 4.8M float4
    const int nu4 = N_USERS * EMB / 4;         // 1.6M
    int i = blockIdx.x * blockDim.x + threadIdx.x;
    if (i >= n4) return;
    float4 v = (i < nu4) ? user4[i] : item4[i - nu4];
    out4[i] = v;                               // acc starts at layer-0 embedding (exact)
    half2* h = reinterpret_cast<half2*>(g_ego[0]);
    h[2 * i]     = __floats2half2_rn(v.x, v.y);
    h[2 * i + 1] = __floats2half2_rn(v.z, v.w);
}

// -------- 3) histogram of rows --------
__global__ void k_hist(const int* __restrict__ rows) {
    int e = blockIdx.x * blockDim.x + threadIdx.x;
    if (e < NNZ) atomicAdd(&g_counts[rows[e]], 1);
}

// -------- 4) exclusive scan (3 kernels) --------
__global__ void k_scan1() {
    __shared__ int sh[SCAN_B];
    int tid = threadIdx.x;
    int gid = blockIdx.x * SCAN_B + tid;
    int v = (gid < N_NODES) ? g_counts[gid] : 0;
    sh[tid] = v;
    __syncthreads();
    for (int off = 1; off < SCAN_B; off <<= 1) {
        int t = (tid >= off) ? sh[tid - off] : 0;
        __syncthreads();
        sh[tid] += t;
        __syncthreads();
    }
    int incl = sh[tid];
    if (gid < N_NODES) g_rowptr[gid] = incl - v;     // block-local exclusive
    if (tid == SCAN_B - 1) g_bsums[blockIdx.x] = incl;
}

__global__ void k_scan2() {
    __shared__ int sh[512];
    int tid = threadIdx.x;   // blockDim = 512, NB = 293 <= 512
    int v = (tid < NB) ? g_bsums[tid] : 0;
    sh[tid] = v;
    __syncthreads();
    for (int off = 1; off < 512; off <<= 1) {
        int t = (tid >= off) ? sh[tid - off] : 0;
        __syncthreads();
        sh[tid] += t;
        __syncthreads();
    }
    if (tid < NB) g_bsums[tid] = sh[tid] - v;        // exclusive
}

__global__ void k_scan3() {
    int gid = blockIdx.x * SCAN_B + threadIdx.x;
    if (gid < N_NODES) {
        int p = g_rowptr[gid] + g_bsums[blockIdx.x];
        g_rowptr[gid] = p;
        g_cursor[gid] = p;                            // scatter cursors start at row base
    }
    if (gid == 0) g_rowptr[N_NODES] = NNZ;
}

// -------- 5) scatter COO -> CSR (packed meta) --------
__global__ void k_scatter(const int* __restrict__ rows,
                          const int* __restrict__ cols,
                          const float* __restrict__ vals) {
    int e = blockIdx.x * blockDim.x + threadIdx.x;
    if (e >= NNZ) return;
    int r = rows[e];
    int idx = atomicAdd(&g_cursor[r], 1);
    g_edge[idx] = make_int2(cols[e], __float_as_int(vals[e]));
}

// -------- 6) warp-per-row SpMM (fp16 gather, fp32 accumulate) --------
__global__ __launch_bounds__(256) void k_spmm(int pin, float2* __restrict__ acc) {
    const half2* __restrict__ ein = reinterpret_cast<const half2*>(g_ego[pin]);
    half2* __restrict__ eout      = reinterpret_cast<half2*>(g_ego[1 - pin]);

    int warp = (blockIdx.x * blockDim.x + threadIdx.x) >> 5;
    int lane = threadIdx.x & 31;
    if (warp >= N_NODES) return;

    int start = g_rowptr[warp];
    int end   = g_rowptr[warp + 1];

    float2 a = make_float2(0.f, 0.f);

    for (int base = start; base < end; base += 32) {
        int rem = end - base;
        int c = 0; float v = 0.f;
        if (lane < rem) {                    // coalesced 8B meta load for up to 32 edges
            int2 ev = __ldg(&g_edge[base + lane]);
            c = ev.x;
            v = __int_as_float(ev.y);
        }
        if (rem >= 32) {
            #pragma unroll
            for (int j = 0; j < 32; j++) {
                int   cj = __shfl_sync(0xffffffffu, c, j);
                float vj = __shfl_sync(0xffffffffu, v, j);
                float2 x = __half22float2(__ldg(ein + (size_t)cj * 32 + lane)); // 128B/warp gather
                a.x = fmaf(vj, x.x, a.x);
                a.y = fmaf(vj, x.y, a.y);
            }
        } else {
            for (int j = 0; j < rem; j++) {
                int   cj = __shfl_sync(0xffffffffu, c, j);
                float vj = __shfl_sync(0xffffffffu, v, j);
                float2 x = __half22float2(__ldg(ein + (size_t)cj * 32 + lane));
                a.x = fmaf(vj, x.x, a.x);
                a.y = fmaf(vj, x.y, a.y);
            }
        }
    }

    size_t o = (size_t)warp * 32 + lane;
    eout[o] = __floats2half2_rn(a.x, a.y);   // next layer's gather operand (fp16)
    float2 t = acc[o];
    t.x += a.x; t.y += a.y;
    acc[o] = t;                              // running fp32 layer sum
}

// -------- 7) final scale by 1/(L+1) = 0.25 --------
__global__ void k_scale(float4* __restrict__ out4) {
    const int n4 = N_NODES * EMB / 4;
    int i = blockIdx.x * blockDim.x + threadIdx.x;
    if (i >= n4) return;
    float4 v = out4[i];
    v.x *= 0.25f; v.y *= 0.25f; v.z *= 0.25f; v.w *= 0.25f;
    out4[i] = v;
}

extern "C" void kernel_launch(void* const* d_in, const int* in_sizes, int n_in,
                              void* d_out, int out_size) {
    const float* user = (const float*)d_in[0];
    const float* item = (const float*)d_in[1];
    const int*   rows = (const int*)d_in[2];
    const int*   cols = (const int*)d_in[3];
    const float* vals = (const float*)d_in[4];
    float* out = (float*)d_out;

    const int T = 256;
    const int n4      = N_NODES * EMB / 4;
    const int gInit   = (n4 + T - 1) / T;
    const int gNodes  = (N_NODES + T - 1) / T;
    const int gEdges  = (NNZ + T - 1) / T;
    const int gSpmm   = ((N_NODES * 32) + T - 1) / T;

    k_zero_counts<<<gNodes, T>>>();
    k_init<<<gInit, T>>>((const float4*)user, (const float4*)item, (float4*)out);
    k_hist<<<gEdges, T>>>(rows);
    k_scan1<<<NB, SCAN_B>>>();
    k_scan2<<<1, 512>>>();
    k_scan3<<<NB, SCAN_B>>>();
    k_scatter<<<gEdges, T>>>(rows, cols, vals);

    int pin = 0;
    for (int layer = 0; layer < 3; layer++) {
        k_spmm<<<gSpmm, T>>>(pin, (float2*)out);
        pin = 1 - pin;
    }
    k_scale<<<gInit, T>>>((float4*)out);
}

// round 3
// speedup vs baseline: 1.3419x; 1.0510x over previous
#include <cuda_runtime.h>
#include <cuda_fp16.h>
#include <cstdint>

#define N_USERS 100000
#define N_ITEMS 200000
#define N_NODES 300000
#define EMB     64
#define NNZ     9600000
#define SCAN_B  1024
#define NB      ((N_NODES + SCAN_B - 1) / SCAN_B)   // 293
#define SPMM_BLOCKS (148 * 8)

// -------- static device scratch (allocation-free) --------
__device__ __half g_ego[2][(size_t)N_NODES * EMB];   // ping-pong fp16 layer embeddings
__device__ int2   g_edge[NNZ];                       // packed (col, val-bits)
__device__ int    g_rowptr[N_NODES + 1];
__device__ int    g_cursor[N_NODES];
__device__ int    g_counts[N_NODES];
__device__ int    g_bsums[NB];

// -------- 1) zero counts --------
__global__ void k_zero_counts() {
    int i = blockIdx.x * blockDim.x + threadIdx.x;
    if (i < N_NODES) g_counts[i] = 0;
}

// -------- 2) init: acc(=d_out) = ego0 (fp32), g_ego[0] = fp16(ego0) --------
__global__ void k_init(const float4* __restrict__ user4,
                       const float4* __restrict__ item4,
                       float4* __restrict__ out4) {
    const int n4  = N_NODES * EMB / 4;         // 4.8M float4
    const int nu4 = N_USERS * EMB / 4;         // 1.6M
    int i = blockIdx.x * blockDim.x + threadIdx.x;
    if (i >= n4) return;
    float4 v = (i < nu4) ? user4[i] : item4[i - nu4];
    out4[i] = v;                               // acc starts at layer-0 embedding (exact)
    half2* h = reinterpret_cast<half2*>(g_ego[0]);
    h[2 * i]     = __floats2half2_rn(v.x, v.y);
    h[2 * i + 1] = __floats2half2_rn(v.z, v.w);
}

// -------- 3) histogram of rows --------
__global__ void k_hist(const int* __restrict__ rows) {
    int e = blockIdx.x * blockDim.x + threadIdx.x;
    if (e < NNZ) atomicAdd(&g_counts[rows[e]], 1);
}

// -------- 4) exclusive scan (3 kernels) --------
__global__ void k_scan1() {
    __shared__ int sh[SCAN_B];
    int tid = threadIdx.x;
    int gid = blockIdx.x * SCAN_B + tid;
    int v = (gid < N_NODES) ? g_counts[gid] : 0;
    sh[tid] = v;
    __syncthreads();
    for (int off = 1; off < SCAN_B; off <<= 1) {
        int t = (tid >= off) ? sh[tid - off] : 0;
        __syncthreads();
        sh[tid] += t;
        __syncthreads();
    }
    int incl = sh[tid];
    if (gid < N_NODES) g_rowptr[gid] = incl - v;     // block-local exclusive
    if (tid == SCAN_B - 1) g_bsums[blockIdx.x] = incl;
}

__global__ void k_scan2() {
    __shared__ int sh[512];
    int tid = threadIdx.x;   // blockDim = 512, NB = 293 <= 512
    int v = (tid < NB) ? g_bsums[tid] : 0;
    sh[tid] = v;
    __syncthreads();
    for (int off = 1; off < 512; off <<= 1) {
        int t = (tid >= off) ? sh[tid - off] : 0;
        __syncthreads();
        sh[tid] += t;
        __syncthreads();
    }
    if (tid < NB) g_bsums[tid] = sh[tid] - v;        // exclusive
}

__global__ void k_scan3() {
    int gid = blockIdx.x * SCAN_B + threadIdx.x;
    if (gid < N_NODES) {
        int p = g_rowptr[gid] + g_bsums[blockIdx.x];
        g_rowptr[gid] = p;
        g_cursor[gid] = p;                            // scatter cursors start at row base
    }
    if (gid == 0) g_rowptr[N_NODES] = NNZ;
}

// -------- 5) scatter COO -> CSR (packed meta) --------
__global__ void k_scatter(const int* __restrict__ rows,
                          const int* __restrict__ cols,
                          const float* __restrict__ vals) {
    int e = blockIdx.x * blockDim.x + threadIdx.x;
    if (e >= NNZ) return;
    int r = rows[e];
    int idx = atomicAdd(&g_cursor[r], 1);
    g_edge[idx] = make_int2(cols[e], __float_as_int(vals[e]));
}

// -------- 6) persistent warp-per-row SpMM (fp16 gather, fp32 accumulate) --------
// last==0: eout = fp16(a); acc += a
// last==1: acc = (acc + a) * 0.25   (fused final mean; no eout write)
__global__ __launch_bounds__(256) void k_spmm(int pin, int last, float2* __restrict__ acc) {
    const half2* __restrict__ ein = reinterpret_cast<const half2*>(g_ego[pin]);
    half2* __restrict__ eout      = reinterpret_cast<half2*>(g_ego[1 - pin]);

    const int lane   = threadIdx.x & 31;
    const int warp0  = (blockIdx.x * blockDim.x + threadIdx.x) >> 5;
    const int nwarps = (gridDim.x * blockDim.x) >> 5;

    for (int row = warp0; row < N_NODES; row += nwarps) {
        int start = g_rowptr[row];
        int end   = g_rowptr[row + 1];

        float2 a = make_float2(0.f, 0.f);

        for (int base = start; base < end; base += 32) {
            int rem = end - base;
            int c = 0; float v = 0.f;
            if (lane < rem) {                    // coalesced 8B meta load for up to 32 edges
                int2 ev = __ldg(&g_edge[base + lane]);
                c = ev.x;
                v = __int_as_float(ev.y);
            }
            if (rem >= 32) {
                #pragma unroll
                for (int j = 0; j < 32; j++) {
                    int   cj = __shfl_sync(0xffffffffu, c, j);
                    float vj = __shfl_sync(0xffffffffu, v, j);
                    float2 x = __half22float2(__ldg(ein + (size_t)cj * 32 + lane)); // 128B/warp gather
                    a.x = fmaf(vj, x.x, a.x);
                    a.y = fmaf(vj, x.y, a.y);
                }
            } else {
                for (int j = 0; j < rem; j++) {
                    int   cj = __shfl_sync(0xffffffffu, c, j);
                    float vj = __shfl_sync(0xffffffffu, v, j);
                    float2 x = __half22float2(__ldg(ein + (size_t)cj * 32 + lane));
                    a.x = fmaf(vj, x.x, a.x);
                    a.y = fmaf(vj, x.y, a.y);
                }
            }
        }

        size_t o = (size_t)row * 32 + lane;
        if (last) {
            float2 t = acc[o];
            acc[o] = make_float2((t.x + a.x) * 0.25f, (t.y + a.y) * 0.25f);
        } else {
            eout[o] = __floats2half2_rn(a.x, a.y);   // next layer's gather operand (fp16)
            float2 t = acc[o];
            t.x += a.x; t.y += a.y;
            acc[o] = t;                              // running fp32 layer sum
        }
    }
}

extern "C" void kernel_launch(void* const* d_in, const int* in_sizes, int n_in,
                              void* d_out, int out_size) {
    const float* user = (const float*)d_in[0];
    const float* item = (const float*)d_in[1];
    const int*   rows = (const int*)d_in[2];
    const int*   cols = (const int*)d_in[3];
    const float* vals = (const float*)d_in[4];
    float* out = (float*)d_out;

    const int T = 256;
    const int n4      = N_NODES * EMB / 4;
    const int gInit   = (n4 + T - 1) / T;
    const int gNodes  = (N_NODES + T - 1) / T;
    const int gEdges  = (NNZ + T - 1) / T;

    k_zero_counts<<<gNodes, T>>>();
    k_init<<<gInit, T>>>((const float4*)user, (const float4*)item, (float4*)out);
    k_hist<<<gEdges, T>>>(rows);
    k_scan1<<<NB, SCAN_B>>>();
    k_scan2<<<1, 512>>>();
    k_scan3<<<NB, SCAN_B>>>();
    k_scatter<<<gEdges, T>>>(rows, cols, vals);

    k_spmm<<<SPMM_BLOCKS, T>>>(0, 0, (float2*)out);   // layer 1
    k_spmm<<<SPMM_BLOCKS, T>>>(1, 0, (float2*)out);   // layer 2
    k_spmm<<<SPMM_BLOCKS, T>>>(0, 1, (float2*)out);   // layer 3 + fused mean
}